// round 9
// baseline (speedup 1.0000x reference)
#include <cuda_runtime.h>

#define NCLS   8192
#define NBATCH 8192
#define THREADS 256
#define NWARPS (THREADS / 32)
#define NCTAS  1184          // 148 SMs * 8 CTAs/SM, persistent
#define EPSF 1e-8f
#define DEPTH_PARAM 0.1f
#define FULLMASK 0xffffffffu

// Global accumulator + completion counter. Zero-initialized at module load;
// the last-finishing row resets both before the kernel ends, so every
// kernel_launch call starts from identical state.
__device__ double       g_acc;
__device__ unsigned int g_done;

__global__ __launch_bounds__(THREADS)
void chce_fused_kernel(const float* __restrict__ y_pred,
                       const float* __restrict__ y_true,
                       const float* __restrict__ class_w,
                       const int*   __restrict__ tree_paths,
                       const int*   __restrict__ tree_lens,
                       float*       __restrict__ out,
                       int D)
{
    const int tid  = threadIdx.x;
    const int lane = tid & 31;
    const int warp = tid >> 5;

    // Double-buffered combine scratch: warp 0 reads buffer[par] for row i
    // while warps 1..7 may already be filling buffer[par^1] for row i+1.
    __shared__ float sh_v[2][NWARPS];
    __shared__ int   sh_i[2][NWARPS];
    __shared__ float sh_s[2][NWARPS];

    int par = 0;
    for (int b = blockIdx.x; b < NBATCH; b += NCTAS, par ^= 1) {
        const float4* yp = reinterpret_cast<const float4*>(y_pred) + (size_t)b * (NCLS / 4);
        const float4* yt = reinterpret_cast<const float4*>(y_true) + (size_t)b * (NCLS / 4);

        float sumexp = 0.0f;
        float best_v = -3.402823466e38f;
        int   best_i = 0;

        // Fused streaming pass over both rows; evict-first on both streams.
        #pragma unroll
        for (int it = 0; it < (NCLS / 4) / THREADS; ++it) {
            const int idx = tid + it * THREADS;
            float4 t = __ldcs(&yt[idx]);
            float4 p = __ldcs(&yp[idx]);

            sumexp += __expf(p.x) + __expf(p.y) + __expf(p.z) + __expf(p.w);

            const int base = idx * 4;
            if (t.x > best_v) { best_v = t.x; best_i = base + 0; }
            if (t.y > best_v) { best_v = t.y; best_i = base + 1; }
            if (t.z > best_v) { best_v = t.z; best_i = base + 2; }
            if (t.w > best_v) { best_v = t.w; best_i = base + 3; }
        }

        // Warp reduction: sum + (max value, min index on tie).
        #pragma unroll
        for (int off = 16; off > 0; off >>= 1) {
            float ov = __shfl_down_sync(FULLMASK, best_v, off);
            int   oi = __shfl_down_sync(FULLMASK, best_i, off);
            float os = __shfl_down_sync(FULLMASK, sumexp, off);
            sumexp += os;
            if (ov > best_v || (ov == best_v && oi < best_i)) { best_v = ov; best_i = oi; }
        }

        if (lane == 0) { sh_v[par][warp] = best_v; sh_i[par][warp] = best_i; sh_s[par][warp] = sumexp; }
        __syncthreads();
        // Warps 1..NWARPS-1 proceed to the next row's streaming immediately;
        // warp 0 runs the epilogue for this row (hidden behind streaming).

        if (warp == 0) {
            float v = (lane < NWARPS) ? sh_v[par][lane] : -3.402823466e38f;
            int   i = (lane < NWARPS) ? sh_i[par][lane] : 0x7fffffff;
            float s = (lane < NWARPS) ? sh_s[par][lane] : 0.0f;
            #pragma unroll
            for (int off = NWARPS / 2; off > 0; off >>= 1) {
                float ov = __shfl_down_sync(FULLMASK, v, off);
                int   oi = __shfl_down_sync(FULLMASK, i, off);
                float os = __shfl_down_sync(FULLMASK, s, off);
                s += os;
                if (ov > v || (ov == v && oi < i)) { v = ov; i = oi; }
            }
            const float S     = __shfl_sync(FULLMASK, s, 0);
            const int   label = __shfl_sync(FULLMASK, i, 0);
            const float invS  = 1.0f / S;

            const int len = tree_lens[label];

            // Parallel path gather: lane k handles level k.
            float pr = 0.0f;
            if (lane < len && lane < D) {
                const int node = tree_paths[(size_t)label * D + lane];
                pr = expf(y_pred[(size_t)b * NCLS + node]) * invS;
            }

            // Reverse inclusive suffix scan: sarr[k] = sum_{j>=k} pr[j].
            float sarr = pr;
            #pragma unroll
            for (int off = 1; off < 32; off <<= 1) {
                float t = __shfl_down_sync(FULLMASK, sarr, off);
                if (lane + off < 32) sarr += t;
            }
            float snext = __shfl_down_sync(FULLMASK, sarr, 1);
            if (lane == 31) snext = 0.0f;

            // Per-level loss terms (valid: k < len-1).
            float term = 0.0f;
            if (lane < len - 1) {
                const float cond = sarr / (snext + EPSF);
                const float h    = (float)(len - 1 - lane);
                term = expf(-DEPTH_PARAM * h) * logf(cond + EPSF);
            }
            #pragma unroll
            for (int off = 16; off > 0; off >>= 1)
                term += __shfl_down_sync(FULLMASK, term, off);

            if (lane == 0) {
                atomicAdd(&g_acc, (double)(-class_w[label] * term));

                // Last-row-done finalize.
                __threadfence();
                const unsigned ticket = atomicAdd(&g_done, 1u);
                if (ticket == NBATCH - 1) {
                    const unsigned long long raw =
                        atomicExch(reinterpret_cast<unsigned long long*>(&g_acc), 0ull);
                    const double acc = __longlong_as_double((long long)raw);
                    out[0] = (float)(acc / (double)NBATCH);
                    g_done = 0;   // reset for the next launch (stream-ordered)
                }
            }
        }
    }
}

extern "C" void kernel_launch(void* const* d_in, const int* in_sizes, int n_in,
                              void* d_out, int out_size)
{
    const float* y_pred     = (const float*)d_in[0];
    const float* y_true     = (const float*)d_in[1];
    const float* class_w    = (const float*)d_in[2];
    const int*   tree_paths = (const int*)  d_in[3];
    const int*   tree_lens  = (const int*)  d_in[4];

    const int D = in_sizes[3] / NCLS;

    chce_fused_kernel<<<NCTAS, THREADS>>>(y_pred, y_true, class_w,
                                          tree_paths, tree_lens,
                                          (float*)d_out, D);
}

// round 10
// speedup vs baseline: 1.4028x; 1.4028x over previous
#include <cuda_runtime.h>

#define NCLS   8192
#define NBATCH 8192
#define THREADS 256
#define NWARPS (THREADS / 32)
#define EPSF 1e-8f
#define DEPTH_PARAM 0.1f
#define FULLMASK 0xffffffffu

// Global accumulator + completion counter. Zero-initialized at module load;
// the last-finishing row resets both before the kernel ends, so every
// kernel_launch call starts from identical state.
__device__ double       g_acc;
__device__ unsigned int g_done;

__global__ __launch_bounds__(THREADS)
void chce_fused_kernel(const float* __restrict__ y_pred,
                       const float* __restrict__ y_true,
                       const float* __restrict__ class_w,
                       const int*   __restrict__ tree_paths,
                       const int*   __restrict__ tree_lens,
                       float*       __restrict__ out,
                       int D)
{
    const int b   = blockIdx.x;
    const int tid = threadIdx.x;
    const int lane = tid & 31;
    const int warp = tid >> 5;

    __shared__ float        sh_v[NWARPS];
    __shared__ int          sh_i[NWARPS];
    __shared__ float        sh_s[NWARPS];
    __shared__ unsigned int sh_ticket;
    if (tid == 0) sh_ticket = 0;
    __syncthreads();   // only to publish sh_ticket=0 (cheap, once)

    const float4* yp = reinterpret_cast<const float4*>(y_pred) + (size_t)b * (NCLS / 4);
    const float4* yt = reinterpret_cast<const float4*>(y_true) + (size_t)b * (NCLS / 4);

    float sumexp = 0.0f;
    float best_v = -3.402823466e38f;
    int   best_i = 0;

    // Single fused streaming pass over both rows; evict-first on both streams.
    #pragma unroll
    for (int it = 0; it < (NCLS / 4) / THREADS; ++it) {
        const int idx = tid + it * THREADS;
        float4 t = __ldcs(&yt[idx]);
        float4 p = __ldcs(&yp[idx]);

        sumexp += __expf(p.x) + __expf(p.y) + __expf(p.z) + __expf(p.w);

        const int base = idx * 4;
        if (t.x > best_v) { best_v = t.x; best_i = base + 0; }
        if (t.y > best_v) { best_v = t.y; best_i = base + 1; }
        if (t.z > best_v) { best_v = t.z; best_i = base + 2; }
        if (t.w > best_v) { best_v = t.w; best_i = base + 3; }
    }

    // Warp reduction: sum + (max value, min index on tie).
    #pragma unroll
    for (int off = 16; off > 0; off >>= 1) {
        float ov = __shfl_down_sync(FULLMASK, best_v, off);
        int   oi = __shfl_down_sync(FULLMASK, best_i, off);
        float os = __shfl_down_sync(FULLMASK, sumexp, off);
        sumexp += os;
        if (ov > best_v || (ov == best_v && oi < best_i)) { best_v = ov; best_i = oi; }
    }

    // Publish partials; last-arriving warp runs the epilogue, others exit
    // immediately (no full-CTA barrier -> no idle warp slots).
    unsigned int ticket = 0;
    if (lane == 0) {
        sh_v[warp] = best_v; sh_i[warp] = best_i; sh_s[warp] = sumexp;
        __threadfence_block();            // make partials visible before ticket
        ticket = atomicAdd(&sh_ticket, 1u);
    }
    ticket = __shfl_sync(FULLMASK, ticket, 0);
    if (ticket != NWARPS - 1) return;     // 7 warps exit now

    __threadfence_block();                // acquire side: see all partials

    // Cross-warp combine in registers (NWARPS lanes participate).
    volatile float* vv = sh_v;
    volatile int*   vi = sh_i;
    volatile float* vs = sh_s;
    float v = (lane < NWARPS) ? vv[lane] : -3.402823466e38f;
    int   i = (lane < NWARPS) ? vi[lane] : 0x7fffffff;
    float s = (lane < NWARPS) ? vs[lane] : 0.0f;
    #pragma unroll
    for (int off = NWARPS / 2; off > 0; off >>= 1) {
        float ov = __shfl_down_sync(FULLMASK, v, off);
        int   oi = __shfl_down_sync(FULLMASK, i, off);
        float os = __shfl_down_sync(FULLMASK, s, off);
        s += os;
        if (ov > v || (ov == v && oi < i)) { v = ov; i = oi; }
    }
    const float S     = __shfl_sync(FULLMASK, s, 0);
    const int   label = __shfl_sync(FULLMASK, i, 0);
    const float invS  = 1.0f / S;

    const int len = tree_lens[label];     // same addr all lanes: broadcast

    // Parallel path gather: lane k handles level k (pr=0 beyond len).
    float pr = 0.0f;
    if (lane < len && lane < D) {
        const int node = tree_paths[(size_t)label * D + lane];
        pr = expf(y_pred[(size_t)b * NCLS + node]) * invS;
    }

    // Reverse inclusive suffix scan: sarr[k] = sum_{j>=k} pr[j].
    float sarr = pr;
    #pragma unroll
    for (int off = 1; off < 32; off <<= 1) {
        float t = __shfl_down_sync(FULLMASK, sarr, off);
        if (lane + off < 32) sarr += t;
    }
    float snext = __shfl_down_sync(FULLMASK, sarr, 1);
    if (lane == 31) snext = 0.0f;

    // Per-level loss terms (valid: k < len-1).
    float term = 0.0f;
    if (lane < len - 1) {
        const float cond = sarr / (snext + EPSF);
        const float h    = (float)(len - 1 - lane);
        term = expf(-DEPTH_PARAM * h) * logf(cond + EPSF);
    }
    #pragma unroll
    for (int off = 16; off > 0; off >>= 1)
        term += __shfl_down_sync(FULLMASK, term, off);

    if (lane == 0) {
        atomicAdd(&g_acc, (double)(-class_w[label] * term));

        // Last-row-done finalize: make our add visible, then count in.
        __threadfence();
        const unsigned t2 = atomicAdd(&g_done, 1u);
        if (t2 == NBATCH - 1) {
            const unsigned long long raw =
                atomicExch(reinterpret_cast<unsigned long long*>(&g_acc), 0ull);
            const double acc = __longlong_as_double((long long)raw);
            out[0] = (float)(acc / (double)NBATCH);
            g_done = 0;   // reset for the next launch (stream-ordered)
        }
    }
}

extern "C" void kernel_launch(void* const* d_in, const int* in_sizes, int n_in,
                              void* d_out, int out_size)
{
    const float* y_pred     = (const float*)d_in[0];
    const float* y_true     = (const float*)d_in[1];
    const float* class_w    = (const float*)d_in[2];
    const int*   tree_paths = (const int*)  d_in[3];
    const int*   tree_lens  = (const int*)  d_in[4];

    const int D = in_sizes[3] / NCLS;

    chce_fused_kernel<<<NBATCH, THREADS>>>(y_pred, y_true, class_w,
                                           tree_paths, tree_lens,
                                           (float*)d_out, D);
}